// round 2
// baseline (speedup 1.0000x reference)
#include <cuda_runtime.h>
#include <math.h>

// ---------------------------------------------------------------------------
// Butterfly module: gather rows -> 4 rotation layers -> bias+smooth-relu on
// first 8 rows of each 16-block -> 4 rotation layers -> scatter rows.
//
// Warp-split layout: within a warp, lanes 0-15 own rows 0-7 of 16 distinct
// float4 columns; lanes 16-31 own rows 8-15 of the same columns. Strides
// 1/2/4 stay thread-local; stride-8 layers exchange via shfl_xor(16).
// 8 float4 of live data per thread -> <=64 regs -> 4 CTAs/SM.
// ---------------------------------------------------------------------------

#define CURV2 0.01f   // CURVATURE^2 = 0.1^2

__device__ __forceinline__ float smooth_relu(float xa) {
    return 0.5f * (xa + sqrtf(fmaf(xa, xa, CURV2)));
}

__device__ __forceinline__ void rot4(float4& a, float4& b, float c, float s) {
    float4 na, nb;
    na.x = fmaf(c, a.x, s * b.x);  nb.x = fmaf(c, b.x, -s * a.x);
    na.y = fmaf(c, a.y, s * b.y);  nb.y = fmaf(c, b.y, -s * a.y);
    na.z = fmaf(c, a.z, s * b.z);  nb.z = fmaf(c, b.z, -s * a.z);
    na.w = fmaf(c, a.w, s * b.w);  nb.w = fmaf(c, b.w, -s * a.w);
    a = na; b = nb;
}

// Thread-local butterfly layer over the 8-row half, stride S in {1,2,4}.
// cs must already be offset by (layer_base + 4*half): local pair rank p
// plus 4*half equals the global ascending-low rank within the 16-block.
template <int S>
__device__ __forceinline__ void blayer8(float4 v[8], const float2* __restrict__ cs) {
    int p = 0;
#pragma unroll
    for (int i = 0; i < 8; ++i) {
        if ((i & S) == 0) {
            float2 a = cs[p++];
            rot4(v[i], v[i + S], a.x, a.y);
        }
    }
}

__device__ __forceinline__ float4 shfl_xor4(float4 x, int mask) {
    float4 r;
    r.x = __shfl_xor_sync(0xffffffffu, x.x, mask);
    r.y = __shfl_xor_sync(0xffffffffu, x.y, mask);
    r.z = __shfl_xor_sync(0xffffffffu, x.z, mask);
    r.w = __shfl_xor_sync(0xffffffffu, x.w, mask);
    return r;
}

// Stride-8 layer: partner lives in the other half-warp (lane ^ 16).
// Angle rank for pair (i, i+8) is i, for both halves.
__device__ __forceinline__ void blayer8_x(float4 v[8], const float2* __restrict__ cs,
                                          int half) {
#pragma unroll
    for (int i = 0; i < 8; ++i) {
        float2 a = cs[i];
        float4 w = shfl_xor4(v[i], 16);
        float4 nv;
        if (half == 0) {        // own = xl, partner = xh : c*xl + s*xh
            nv.x = fmaf(a.x, v[i].x,  a.y * w.x);
            nv.y = fmaf(a.x, v[i].y,  a.y * w.y);
            nv.z = fmaf(a.x, v[i].z,  a.y * w.z);
            nv.w = fmaf(a.x, v[i].w,  a.y * w.w);
        } else {                // own = xh, partner = xl : -s*xl + c*xh
            nv.x = fmaf(a.x, v[i].x, -a.y * w.x);
            nv.y = fmaf(a.x, v[i].y, -a.y * w.y);
            nv.z = fmaf(a.x, v[i].z, -a.y * w.z);
            nv.w = fmaf(a.x, v[i].w, -a.y * w.w);
        }
        v[i] = nv;
    }
}

__global__ __launch_bounds__(256, 4)
void butterfly_kernel(const float* __restrict__ data,
                      const float* __restrict__ angles,
                      const float* __restrict__ biases,
                      const int*   __restrict__ idx_in,
                      const int*   __restrict__ idx_out,
                      float*       __restrict__ out,
                      int N, int B)
{
    __shared__ float2 cs[64];    // [layer 0..7][pair 0..7] -> (cos, sin)
    __shared__ float  sb[8];     // biases for this 16-block
    __shared__ int    rin[16], rout[16];

    const int tid = threadIdx.x;
    const int blk = blockIdx.y;          // 16-row block index

    if (tid < 64) {
        int l = tid >> 3, p = tid & 7;
        float a = angles[(size_t)l * (N >> 1) + blk * 8 + p];
        float s, c;
        sincosf(a, &s, &c);
        cs[tid] = make_float2(c, s);
    }
    if (tid < 8)  sb[tid] = biases[blk * 8 + tid];
    if (tid < 16) {
        rin[tid]  = idx_in[blk * 16 + tid];
        rout[tid] = idx_out[blk * 16 + tid];
    }
    __syncthreads();

    const int lane  = tid & 31;
    const int half  = lane >> 4;         // 0: rows 0-7, 1: rows 8-15
    const int cidx  = (tid >> 5) * 16 + (lane & 15);   // float4 column in tile
    const int col   = blockIdx.x * (8 * 16 * 4) + cidx * 4;

    const int rbase = half * 8;

    float4 v[8];
#pragma unroll
    for (int i = 0; i < 8; ++i)
        v[i] = *reinterpret_cast<const float4*>(
                   data + (size_t)rin[rbase + i] * B + col);

    const float2* c0 = cs + 4 * half;

    // input layers: strides 1,2,4,8
    blayer8<1>(v, c0 + 0);
    blayer8<2>(v, c0 + 8);
    blayer8<4>(v, c0 + 16);
    blayer8_x (v, cs + 24, half);

    // fused bias + smooth relu on rows 0-7 of the block (half 0 only)
    if (half == 0) {
#pragma unroll
        for (int i = 0; i < 8; ++i) {
            float b = sb[i];
            v[i].x = smooth_relu(v[i].x + b);
            v[i].y = smooth_relu(v[i].y + b);
            v[i].z = smooth_relu(v[i].z + b);
            v[i].w = smooth_relu(v[i].w + b);
        }
    }

    // output layers: strides 1,2,4,8
    blayer8<1>(v, c0 + 32);
    blayer8<2>(v, c0 + 40);
    blayer8<4>(v, c0 + 48);
    blayer8_x (v, cs + 56, half);

#pragma unroll
    for (int i = 0; i < 8; ++i)
        *reinterpret_cast<float4*>(out + (size_t)rout[rbase + i] * B + col) = v[i];
}

// ---------------------------------------------------------------------------
// Rows of `out` NOT targeted by idx_out must be a pass-through of `data`.
// g_covered starts zero (static init). mark sets; copy reads then CLEARS,
// so the flag array returns to all-zero after every replay (graph-safe).
// ---------------------------------------------------------------------------

__device__ unsigned char g_covered[1 << 20];  // supports up to 1M rows

__global__ void mark_flags_kernel(const int* __restrict__ idx_out, int N) {
    int i = blockIdx.x * blockDim.x + threadIdx.x;
    if (i < N) g_covered[idx_out[i]] = 1;
}

__global__ __launch_bounds__(256)
void copy_uncovered_kernel(const float* __restrict__ data,
                           float* __restrict__ out, int B) {
    int row = blockIdx.x;
    unsigned char cov;
    if (threadIdx.x == 0) {
        cov = g_covered[row];
        g_covered[row] = 0;          // self-reset for next replay
    }
    cov = (unsigned char)__shfl_sync(0xffffffffu, (int)cov, 0);
    __shared__ int s_cov;
    if (threadIdx.x == 0) s_cov = cov;
    __syncthreads();
    if (s_cov) return;
    const float4* src = reinterpret_cast<const float4*>(data + (size_t)row * B);
    float4*       dst = reinterpret_cast<float4*>(out + (size_t)row * B);
    for (int i = threadIdx.x; i < (B >> 2); i += blockDim.x)
        dst[i] = src[i];
}

extern "C" void kernel_launch(void* const* d_in, const int* in_sizes, int n_in,
                              void* d_out, int out_size)
{
    const float* data    = (const float*)d_in[0];
    const float* angles  = (const float*)d_in[1];
    const float* biases  = (const float*)d_in[2];
    const int*   idx_in  = (const int*)d_in[3];
    const int*   idx_out = (const int*)d_in[4];
    float*       out     = (float*)d_out;

    const int N = in_sizes[3];            // number of gathered rows (4096)
    const int B = in_sizes[0] / N;        // row width (8192)
    const int R = out_size / B;           // rows in data/out

    // pass-through for rows not written by the scatter (2 launches)
    mark_flags_kernel<<<(N + 255) / 256, 256>>>(idx_out, N);
    copy_uncovered_kernel<<<R, 256>>>(data, out, B);

    // main fused butterfly: tile = 16 rows x 512 floats
    dim3 grid(B / 512, N / 16);
    butterfly_kernel<<<grid, 256>>>(data, angles, biases, idx_in, idx_out,
                                    out, N, B);
}